// round 6
// baseline (speedup 1.0000x reference)
#include <cuda_runtime.h>
#include <cuda_bf16.h>
#include <math.h>

// Problem constants (fixed by the dataset)
#define Bb   4
#define Ss   2048
#define Dd   512
#define Hh   8
#define DK   64
#define Rr   8
#define TR   16
#define NBH  (Bb*Hh)                // 32
#define NNODES (NBH*Ss)             // 65536
#define NEDGE  (NBH*TR*Ss)          // 1048576

// ---------------- scratch (device globals; no allocation allowed) -------------
__device__ float g_q[NBH*Ss*DK];
__device__ float g_k[NBH*Ss*DK];
__device__ float g_v[NBH*Ss*DK];
__device__ float g_e[NEDGE];
__device__ int   g_cnt[NNODES];
__device__ int   g_off[NBH*(Ss+1)];
__device__ int   g_info[NEDGE];
__device__ float g_val[NEDGE];
__device__ float g_attn[Bb*Ss*Dd];   // row m=b*S+s, col h*64+d

// ======================= helpers =============================================
__device__ __forceinline__ unsigned packbf2(float x, float y){
    __nv_bfloat162 t = __floats2bfloat162_rn(x, y);
    return *(unsigned*)&t;
}
__device__ __forceinline__ void split2(float2 v, unsigned& hi, unsigned& lo){
    float hx = __bfloat162float(__float2bfloat16(v.x));
    float hy = __bfloat162float(__float2bfloat16(v.y));
    hi = packbf2(hx, hy);
    lo = packbf2(v.x - hx, v.y - hy);
}
__device__ __forceinline__ void mma_bf16(float* d, const unsigned* a, const unsigned* b){
    asm volatile(
        "mma.sync.aligned.m16n8k16.row.col.f32.bf16.bf16.f32 "
        "{%0,%1,%2,%3}, {%4,%5,%6,%7}, {%8,%9}, {%0,%1,%2,%3};"
        : "+f"(d[0]), "+f"(d[1]), "+f"(d[2]), "+f"(d[3])
        : "r"(a[0]), "r"(a[1]), "r"(a[2]), "r"(a[3]), "r"(b[0]), "r"(b[1]));
}

// ======== GEMM via direct-gmem fragments: C[m,n]=sum_k A[m,k]*W[n,k]+bias[n] ==
// M=8192, N=512, K=512. BM=128, BN=64, 8 warps (4M x 2N), warp tile 32x32.
// No smem, no syncthreads: each lane LDGs its own mma fragment elements
// (float2, 32B-contiguous per quad), splits fp32 -> bf16 hi/lo in registers,
// 3-term MMA (hi*hi + hi*lo + lo*hi) for fp32-grade accuracy.
// mode 0: fused QKV (blockIdx.z selects tensor set, dst = g_q/g_k/g_v scattered)
// mode 1: A = g_attn, dst = C_ext flat
__global__ __launch_bounds__(256, 2) void gemm_tc(
    const float* __restrict__ A0, const float* __restrict__ A1,
    const float* __restrict__ A2,
    const float* __restrict__ W0, const float* __restrict__ W1,
    const float* __restrict__ W2,
    const float* __restrict__ B0, const float* __restrict__ B1,
    const float* __restrict__ B2,
    float* __restrict__ C_ext, int mode)
{
    const int z = blockIdx.z;
    const float* A;
    const float* W;
    const float* bias;
    float* dst;
    if (mode == 0) {
        A = (z == 0) ? A0 : (z == 1) ? A1 : A2;
        W = (z == 0) ? W0 : (z == 1) ? W1 : W2;
        bias = (z == 0) ? B0 : (z == 1) ? B1 : B2;
        dst = (z == 0) ? g_q : (z == 1) ? g_k : g_v;
    } else {
        A = g_attn; W = W0; bias = B0; dst = C_ext;
    }

    const int tid = threadIdx.x;
    const int wid = tid >> 5, lane = tid & 31;
    const int wm = wid & 3, wn = wid >> 2;
    const int m0 = blockIdx.y * 128, n0 = blockIdx.x * 64;

    const int r4 = lane >> 2;            // 0..7
    const int c2 = (lane & 3) * 2;       // 0,2,4,6

    // fragment base pointers
    const float* pA = A + (size_t)(m0 + wm * 32 + r4) * Dd + c2;
    const float* pB = W + (size_t)(n0 + wn * 32 + r4) * Dd + c2;

    float acc[2][4][4];
#pragma unroll
    for (int mt = 0; mt < 2; mt++)
#pragma unroll
        for (int nt = 0; nt < 4; nt++)
#pragma unroll
            for (int i = 0; i < 4; i++) acc[mt][nt][i] = 0.f;

    for (int k0 = 0; k0 < Dd; k0 += 16) {
        // ---- load fragments from gmem (16 x LDG.64, high MLP) ----
        float2 fa[2][4], fb[4][2];
#pragma unroll
        for (int mt = 0; mt < 2; mt++) {
            const float* p = pA + mt * 16 * Dd + k0;
            fa[mt][0] = *(const float2*)(p);
            fa[mt][1] = *(const float2*)(p + 8 * Dd);
            fa[mt][2] = *(const float2*)(p + 8);
            fa[mt][3] = *(const float2*)(p + 8 * Dd + 8);
        }
#pragma unroll
        for (int nt = 0; nt < 4; nt++) {
            const float* p = pB + nt * 8 * Dd + k0;
            fb[nt][0] = *(const float2*)(p);
            fb[nt][1] = *(const float2*)(p + 8);
        }
        // ---- split to bf16 hi/lo ----
        unsigned ah[2][4], al[2][4], bh[4][2], bl[4][2];
#pragma unroll
        for (int mt = 0; mt < 2; mt++)
#pragma unroll
            for (int i = 0; i < 4; i++) split2(fa[mt][i], ah[mt][i], al[mt][i]);
#pragma unroll
        for (int nt = 0; nt < 4; nt++)
#pragma unroll
            for (int i = 0; i < 2; i++) split2(fb[nt][i], bh[nt][i], bl[nt][i]);
        // ---- 3-term MMAs ----
#pragma unroll
        for (int mt = 0; mt < 2; mt++)
#pragma unroll
            for (int nt = 0; nt < 4; nt++) {
                mma_bf16(acc[mt][nt], ah[mt], bh[nt]);
                mma_bf16(acc[mt][nt], ah[mt], bl[nt]);
                mma_bf16(acc[mt][nt], al[mt], bh[nt]);
            }
    }

    // -------- epilogue: fragments -> gmem with bias --------
#pragma unroll
    for (int nt = 0; nt < 4; nt++) {
        const int ncol = n0 + wn * 32 + nt * 8 + 2 * (lane & 3);
        const float b0 = bias[ncol], b1 = bias[ncol + 1];
#pragma unroll
        for (int mt = 0; mt < 2; mt++) {
            const int r0 = m0 + wm * 32 + mt * 16 + (lane >> 2);
            float2 v0 = make_float2(acc[mt][nt][0] + b0, acc[mt][nt][1] + b1);
            float2 v1 = make_float2(acc[mt][nt][2] + b0, acc[mt][nt][3] + b1);
            if (mode == 1) {
                *(float2*)(dst + (size_t)r0 * Dd + ncol) = v0;
                *(float2*)(dst + (size_t)(r0 + 8) * Dd + ncol) = v1;
            } else {
                const int h = ncol >> 6, d = ncol & 63;
                int b = r0 >> 11, s = r0 & (Ss - 1);
                *(float2*)(dst + (size_t)(((b * Hh + h) * Ss + s)) * DK + d) = v0;
                b = (r0 + 8) >> 11; s = (r0 + 8) & (Ss - 1);
                *(float2*)(dst + (size_t)(((b * Hh + h) * Ss + s)) * DK + d) = v1;
            }
        }
    }
}

// ---------------- zero counters -------------------------------------------
__global__ void k_zero()
{
    int i = blockIdx.x * 256 + threadIdx.x;
    if (i < NNODES) g_cnt[i] = 0;
}

// ---------------- per-edge score + exp + count -----------------------------
__global__ __launch_bounds__(256) void k_edges(
    const int* __restrict__ snod, const int* __restrict__ enod,
    const float* __restrict__ rq, const float* __restrict__ rk)
{
    int gt = blockIdx.x * 256 + threadIdx.x;
    int e = gt >> 4;
    int sub = gt & 15;
    int s = e & (Ss - 1);
    int j = (e >> 11) & 15;
    int bh = e >> 15;
    int h = bh & (Hh - 1);
    int jm = j & (Rr - 1);
    int nidx = (bh * Rr + jm) * Ss + s;
    int sv = snod[nidx];
    int ev = enod[nidx];
    bool masked = (j == 0) || (sv < 0);
    int s0 = sv < 0 ? 0 : sv;
    int qn = (j < Rr) ? ev : s0;
    int kn = (j < Rr) ? s0 : ev;
    qn &= (Ss - 1); kn &= (Ss - 1);

    const float4 qv  = *(const float4*)&g_q[(size_t)(bh * Ss + qn) * DK + sub * 4];
    const float4 kv  = *(const float4*)&g_k[(size_t)(bh * Ss + kn) * DK + sub * 4];
    const float4 rqv = *(const float4*)&rq[(h * TR + j) * DK + sub * 4];
    const float4 rkv = *(const float4*)&rk[(h * TR + j) * DK + sub * 4];

    float p = qv.x * (kv.x + rkv.x) + rqv.x * kv.x
            + qv.y * (kv.y + rkv.y) + rqv.y * kv.y
            + qv.z * (kv.z + rkv.z) + rqv.z * kv.z
            + qv.w * (kv.w + rkv.w) + rqv.w * kv.w;
#pragma unroll
    for (int off = 8; off; off >>= 1)
        p += __shfl_xor_sync(0xffffffffu, p, off);

    if (sub == 0 && !masked) {
        float exv = __expf(p * (1.0f / 24.0f));
        g_e[e] = exv;
        atomicAdd(&g_cnt[bh * Ss + qn], 1);
    }
}

// ---------------- exclusive scan of per-node counts per (b,h) --------------
__global__ __launch_bounds__(256) void k_scan()
{
    __shared__ int partial[256];
    int bh = blockIdx.x;
    int t = threadIdx.x;
    int base = bh * Ss + t * 8;
    int c[8]; int sum = 0;
#pragma unroll
    for (int i = 0; i < 8; i++) { c[i] = g_cnt[base + i]; sum += c[i]; }
    partial[t] = sum;
    __syncthreads();
    for (int off = 1; off < 256; off <<= 1) {
        int v = (t >= off) ? partial[t - off] : 0;
        __syncthreads();
        partial[t] += v;
        __syncthreads();
    }
    int run = partial[t] - sum;
    int obase = bh * (Ss + 1) + t * 8;
#pragma unroll
    for (int i = 0; i < 8; i++) { g_off[obase + i] = run; run += c[i]; }
    if (t == 255) g_off[bh * (Ss + 1) + Ss] = run;
#pragma unroll
    for (int i = 0; i < 8; i++) g_cnt[base + i] = 0;
}

// ---------------- CSR fill ---------------------------------------------------
__global__ __launch_bounds__(256) void k_fill(
    const int* __restrict__ snod, const int* __restrict__ enod)
{
    int e = blockIdx.x * 256 + threadIdx.x;
    int s = e & (Ss - 1);
    int j = (e >> 11) & 15;
    int bh = e >> 15;
    int jm = j & (Rr - 1);
    int nidx = (bh * Rr + jm) * Ss + s;
    int sv = snod[nidx];
    if (j == 0 || sv < 0) return;
    int ev = enod[nidx];
    int qn = (j < Rr) ? ev : sv;
    int kn = (j < Rr) ? sv : ev;
    qn &= (Ss - 1); kn &= (Ss - 1);
    int pos = g_off[bh * (Ss + 1) + qn] + atomicAdd(&g_cnt[bh * Ss + qn], 1);
    int idx = bh * (TR * Ss) + pos;
    g_info[idx] = kn | (j << 12);
    g_val[idx] = g_e[e];
}

// ---------------- per-node gather + softmax + weighted sum -------------------
__global__ __launch_bounds__(256) void k_aggr(const float* __restrict__ rv)
{
    int w = (blockIdx.x * 256 + threadIdx.x) >> 5;
    int lane = threadIdx.x & 31;
    int bh = w >> 11;
    int n = w & (Ss - 1);
    int h = bh & (Hh - 1), b = bh >> 3;
    int obase = bh * (Ss + 1) + n;
    int beg = g_off[obase], end = g_off[obase + 1];
    float acc0 = 0.f, acc1 = 0.f, ds = 0.f;
    int cbase = bh * (TR * Ss);
    for (int i = beg; i < end; i++) {
        int info = g_info[cbase + i];
        float evv = g_val[cbase + i];
        int kn = info & 0xFFF;
        int j = info >> 12;
        size_t vb = (size_t)(bh * Ss + kn) * DK;
        int rb = (h * TR + j) * DK;
        acc0 += evv * (g_v[vb + lane] + rv[rb + lane]);
        acc1 += evv * (g_v[vb + 32 + lane] + rv[rb + 32 + lane]);
        ds += evv;
    }
    float inv = ds > 0.f ? 1.f / ds : 0.f;
    size_t ob = (size_t)((b * Ss + n) * Hh + h) * DK;
    g_attn[ob + lane] = acc0 * inv;
    g_attn[ob + 32 + lane] = acc1 * inv;
}

// ---------------- launch --------------------------------------------------
extern "C" void kernel_launch(void* const* d_in, const int* in_sizes, int n_in,
                              void* d_out, int out_size)
{
    const float* query = (const float*)d_in[0];
    const float* key   = (const float*)d_in[1];
    const float* value = (const float*)d_in[2];
    const int*   snod  = (const int*)d_in[3];
    const int*   enod  = (const int*)d_in[4];
    const float* rel_q = (const float*)d_in[5];
    const float* rel_k = (const float*)d_in[6];
    const float* rel_v = (const float*)d_in[7];
    const float* Wq = (const float*)d_in[8];
    const float* bq = (const float*)d_in[9];
    const float* Wk = (const float*)d_in[10];
    const float* bk = (const float*)d_in[11];
    const float* Wv = (const float*)d_in[12];
    const float* bv = (const float*)d_in[13];
    const float* Wo = (const float*)d_in[14];
    const float* bo = (const float*)d_in[15];
    float* out = (float*)d_out;

    dim3 gq(Dd / 64, (Bb * Ss) / 128, 3);   // fused QKV: 1536 CTAs
    dim3 go(Dd / 64, (Bb * Ss) / 128, 1);   // output projection

    k_zero<<<NNODES / 256, 256>>>();
    gemm_tc<<<gq, 256>>>(query, key, value, Wq, Wk, Wv, bq, bk, bv, nullptr, 0);
    k_edges<<<(size_t)NEDGE * 16 / 256, 256>>>(snod, enod, rel_q, rel_k);
    k_scan<<<NBH, 256>>>();
    k_fill<<<NEDGE / 256, 256>>>(snod, enod);
    k_aggr<<<NNODES * 32 / 256, 256>>>(rel_v);
    gemm_tc<<<go, 256>>>(nullptr, nullptr, nullptr, Wo, nullptr, nullptr,
                         bo, nullptr, nullptr, out, 1);
}

// round 8
// speedup vs baseline: 1.5738x; 1.5738x over previous
#include <cuda_runtime.h>
#include <cuda_fp16.h>
#include <math.h>

// Problem constants (fixed by the dataset)
#define Bb   4
#define Ss   2048
#define Dd   512
#define Hh   8
#define DK   64
#define Rr   8
#define TR   16
#define NBH  (Bb*Hh)                // 32
#define NNODES (NBH*Ss)             // 65536
#define NEDGE  (NBH*TR*Ss)          // 1048576
#define MROWS (Bb*Ss)               // 8192

// ---------------- scratch (device globals; no allocation allowed) -------------
__device__ float g_q[NBH*Ss*DK];
__device__ float g_k[NBH*Ss*DK];
__device__ float g_v[NBH*Ss*DK];
__device__ float g_e[NEDGE];
__device__ int   g_cnt[NNODES];
__device__ int   g_off[NBH*(Ss+1)];
__device__ int   g_info[NEDGE];
__device__ float g_val[NEDGE];
__device__ __align__(16) __half g_ah[3*MROWS*Dd];   // fp16 inputs (q,k,v)
__device__ __align__(16) __half g_wh[4*Dd*Dd];      // weight hi
__device__ __align__(16) __half g_wl[4*Dd*Dd];      // weight lo
__device__ __align__(16) __half g_atth[MROWS*Dd];   // attn output fp16

// ======================= helpers =============================================
__device__ __forceinline__ unsigned su32(const void* p){
    unsigned a;
    asm("{ .reg .u64 t; cvta.to.shared.u64 t, %1; cvt.u32.u64 %0, t; }"
        : "=r"(a) : "l"(p));
    return a;
}
__device__ __forceinline__ void cpa16(unsigned dst, const void* src){
    asm volatile("cp.async.cg.shared.global [%0], [%1], 16;"
                 :: "r"(dst), "l"(src));
}
__device__ __forceinline__ void cpa_commit(){
    asm volatile("cp.async.commit_group;");
}
__device__ __forceinline__ void cpa_wait2(){
    asm volatile("cp.async.wait_group 2;");
}
__device__ __forceinline__ void ldmx4(unsigned* r, unsigned addr){
    asm volatile("ldmatrix.sync.aligned.m8n8.x4.shared.b16 {%0,%1,%2,%3}, [%4];"
                 : "=r"(r[0]), "=r"(r[1]), "=r"(r[2]), "=r"(r[3]) : "r"(addr));
}
__device__ __forceinline__ void mma_f16(float* d, const unsigned* a, const unsigned* b){
    asm volatile(
        "mma.sync.aligned.m16n8k16.row.col.f32.f16.f16.f32 "
        "{%0,%1,%2,%3}, {%4,%5,%6,%7}, {%8,%9}, {%0,%1,%2,%3};"
        : "+f"(d[0]), "+f"(d[1]), "+f"(d[2]), "+f"(d[3])
        : "r"(a[0]), "r"(a[1]), "r"(a[2]), "r"(a[3]), "r"(b[0]), "r"(b[1]));
}
// 64-byte rows, 16B-granule XOR swizzle: conflict-free ldmatrix (validated R4/R5)
__device__ __forceinline__ unsigned swz(unsigned row, unsigned kb){
    return row * 64u + ((((kb >> 4) ^ ((row >> 1) & 3u)) << 4) | (kb & 15u));
}

// ---------------- conversion pre-passes --------------------------------------
// weights -> fp16 hi/lo.  grid (Dd*Dd/4/256, 4)
__global__ __launch_bounds__(256) void conv_w(
    const float* __restrict__ Wq, const float* __restrict__ Wk,
    const float* __restrict__ Wv, const float* __restrict__ Wo)
{
    const int z = blockIdx.y;
    const float* W = (z == 0) ? Wq : (z == 1) ? Wk : (z == 2) ? Wv : Wo;
    const int i = blockIdx.x * 256 + threadIdx.x;        // float4 index
    float4 v = ((const float4*)W)[i];
    __half hx = __float2half(v.x), hy = __float2half(v.y);
    __half hz = __float2half(v.z), hw = __float2half(v.w);
    const size_t o = (size_t)z * (Dd*Dd) + (size_t)i * 4;
    *(__half2*)&g_wh[o]     = __halves2half2(hx, hy);
    *(__half2*)&g_wh[o + 2] = __halves2half2(hz, hw);
    *(__half2*)&g_wl[o]     = __halves2half2(__float2half(v.x - __half2float(hx)),
                                             __float2half(v.y - __half2float(hy)));
    *(__half2*)&g_wl[o + 2] = __halves2half2(__float2half(v.z - __half2float(hz)),
                                             __float2half(v.w - __half2float(hw)));
}

// inputs -> fp16 (hi only).  grid (MROWS*Dd/4/256, 3). also zeroes g_cnt.
__global__ __launch_bounds__(256) void conv_in(
    const float* __restrict__ q, const float* __restrict__ k,
    const float* __restrict__ v)
{
    const int z = blockIdx.y;
    const float* X = (z == 0) ? q : (z == 1) ? k : v;
    const int i = blockIdx.x * 256 + threadIdx.x;        // float4 index
    if (z == 0 && i < NNODES) g_cnt[i] = 0;
    float4 val = ((const float4*)X)[i];
    const size_t o = (size_t)z * (MROWS*Dd) + (size_t)i * 4;
    *(__half2*)&g_ah[o]     = __floats2half2_rn(val.x, val.y);
    *(__half2*)&g_ah[o + 2] = __floats2half2_rn(val.z, val.w);
}

// ======== fp16 tensor-core GEMM: C[m,n]=sum_k A[m,k]*W[n,k]+bias[n] ==========
// M=8192, N=512, K=512. BM=128, BN=64, BK=32; 256 thr, 8 warps (4M x 2N),
// warp tile 32x32. cp.async 4-stage pipeline, 2-term split: Ah*(Wh+Wl).
// mode 0: fused QKV (z selects set; dst = g_q/g_k/g_v scattered [B,H,S,dk])
// mode 1: A = g_atth, dst = C_ext flat
#define STG_BH 8192
#define STG_BL 12288
#define STAGE  16384

__global__ __launch_bounds__(256, 2) void gemm_tc(
    const float* __restrict__ B0, const float* __restrict__ B1,
    const float* __restrict__ B2, float* __restrict__ C_ext, int mode)
{
    extern __shared__ char dsm[];
    const unsigned sb = su32(dsm);

    const int z = blockIdx.z;
    const __half* A;
    const __half* Wh;
    const __half* Wl;
    const float* bias;
    float* dst;
    if (mode == 0) {
        A = g_ah + (size_t)z * (MROWS*Dd);
        Wh = g_wh + (size_t)z * (Dd*Dd);
        Wl = g_wl + (size_t)z * (Dd*Dd);
        bias = (z == 0) ? B0 : (z == 1) ? B1 : B2;
        dst = (z == 0) ? g_q : (z == 1) ? g_k : g_v;
    } else {
        A = g_atth;
        Wh = g_wh + (size_t)3 * (Dd*Dd);
        Wl = g_wl + (size_t)3 * (Dd*Dd);
        bias = B0;
        dst = C_ext;
    }

    const int tid = threadIdx.x;
    const int wid = tid >> 5, lane = tid & 31;
    const int wm = wid & 3, wn = wid >> 2;
    const int m0 = blockIdx.y * 128, n0 = blockIdx.x * 64;

    // cp.async mappings
    const int arow = tid >> 1;                  // 0..127
    const int ap0 = (2 * tid) & 3;              // 0 or 2 (pieces ap0, ap0+1)
    const int brow = tid >> 2, bp = tid & 3;    // 0..63, piece
    const __half* Asrc = A + (size_t)(m0 + arow) * Dd + ap0 * 8;
    const __half* Whsrc = Wh + (size_t)(n0 + brow) * Dd + bp * 8;
    const __half* Wlsrc = Wl + (size_t)(n0 + brow) * Dd + bp * 8;
    const unsigned dA0 = swz(arow, ap0 * 16);
    const unsigned dA1 = swz(arow, ap0 * 16 + 16);
    const unsigned dB  = swz(brow, bp * 16);

    float acc[2][4][4];
#pragma unroll
    for (int mt = 0; mt < 2; mt++)
#pragma unroll
        for (int nt = 0; nt < 4; nt++)
#pragma unroll
            for (int i = 0; i < 4; i++) acc[mt][nt][i] = 0.f;

    // prologue: stages for chunks 0..2
#pragma unroll
    for (int c = 0; c < 3; c++) {
        const unsigned st = sb + c * STAGE;
        cpa16(st + dA0, Asrc + c * 32);
        cpa16(st + dA1, Asrc + c * 32 + 8);
        cpa16(st + STG_BH + dB, Whsrc + c * 32);
        cpa16(st + STG_BL + dB, Wlsrc + c * 32);
        cpa_commit();
    }

    for (int c = 0; c < 16; c++) {
        cpa_wait2();
        __syncthreads();
        if (c + 3 < 16) {
            const unsigned st = sb + ((c + 3) & 3) * STAGE;
            cpa16(st + dA0, Asrc + (c + 3) * 32);
            cpa16(st + dA1, Asrc + (c + 3) * 32 + 8);
            cpa16(st + STG_BH + dB, Whsrc + (c + 3) * 32);
            cpa16(st + STG_BL + dB, Wlsrc + (c + 3) * 32);
        }
        cpa_commit();   // possibly empty group keeps wait count consistent

        const unsigned st = sb + (c & 3) * STAGE;
#pragma unroll
        for (int ks = 0; ks < 2; ks++) {
            const unsigned kb = ks * 32;
            unsigned ah[2][4], bh[4][2], bl[4][2];
#pragma unroll
            for (int mt = 0; mt < 2; mt++) {
                unsigned r = wm * 32 + mt * 16 + (lane & 15);
                unsigned kbyte = kb + (lane >> 4) * 16;
                ldmx4(ah[mt], st + swz(r, kbyte));
            }
#pragma unroll
            for (int p = 0; p < 2; p++) {
                unsigned r = wn * 32 + p * 16 + (lane & 7) + ((lane >> 4) << 3);
                unsigned kbyte = kb + ((lane >> 3) & 1) * 16;
                unsigned t[4];
                ldmx4(t, st + STG_BH + swz(r, kbyte));
                bh[2*p][0] = t[0]; bh[2*p][1] = t[1];
                bh[2*p+1][0] = t[2]; bh[2*p+1][1] = t[3];
                ldmx4(t, st + STG_BL + swz(r, kbyte));
                bl[2*p][0] = t[0]; bl[2*p][1] = t[1];
                bl[2*p+1][0] = t[2]; bl[2*p+1][1] = t[3];
            }
#pragma unroll
            for (int mt = 0; mt < 2; mt++)
#pragma unroll
                for (int nt = 0; nt < 4; nt++) {
                    mma_f16(acc[mt][nt], ah[mt], bh[nt]);
                    mma_f16(acc[mt][nt], ah[mt], bl[nt]);
                }
        }
        __syncthreads();
    }

    // -------- epilogue: fragments -> gmem with bias --------
#pragma unroll
    for (int nt = 0; nt < 4; nt++) {
        const int ncol = n0 + wn * 32 + nt * 8 + 2 * (lane & 3);
        const float b0 = bias[ncol], b1 = bias[ncol + 1];
#pragma unroll
        for (int mt = 0; mt < 2; mt++) {
            const int r0 = m0 + wm * 32 + mt * 16 + (lane >> 2);
            float2 v0 = make_float2(acc[mt][nt][0] + b0, acc[mt][nt][1] + b1);
            float2 v1 = make_float2(acc[mt][nt][2] + b0, acc[mt][nt][3] + b1);
            if (mode == 1) {
                *(float2*)(dst + (size_t)r0 * Dd + ncol) = v0;
                *(float2*)(dst + (size_t)(r0 + 8) * Dd + ncol) = v1;
            } else {
                const int h = ncol >> 6, d = ncol & 63;
                int b = r0 >> 11, s = r0 & (Ss - 1);
                *(float2*)(dst + (size_t)(((b * Hh + h) * Ss + s)) * DK + d) = v0;
                b = (r0 + 8) >> 11; s = (r0 + 8) & (Ss - 1);
                *(float2*)(dst + (size_t)(((b * Hh + h) * Ss + s)) * DK + d) = v1;
            }
        }
    }
}

// ---------------- per-edge score + exp + count -----------------------------
__global__ __launch_bounds__(256) void k_edges(
    const int* __restrict__ snod, const int* __restrict__ enod,
    const float* __restrict__ rq, const float* __restrict__ rk)
{
    int gt = blockIdx.x * 256 + threadIdx.x;
    int e = gt >> 4;
    int sub = gt & 15;
    int s = e & (Ss - 1);
    int j = (e >> 11) & 15;
    int bh = e >> 15;
    int h = bh & (Hh - 1);
    int jm = j & (Rr - 1);
    int nidx = (bh * Rr + jm) * Ss + s;
    int sv = snod[nidx];
    int ev = enod[nidx];
    bool masked = (j == 0) || (sv < 0);
    int s0 = sv < 0 ? 0 : sv;
    int qn = (j < Rr) ? ev : s0;
    int kn = (j < Rr) ? s0 : ev;
    qn &= (Ss - 1); kn &= (Ss - 1);

    const float4 qv  = *(const float4*)&g_q[(size_t)(bh * Ss + qn) * DK + sub * 4];
    const float4 kv  = *(const float4*)&g_k[(size_t)(bh * Ss + kn) * DK + sub * 4];
    const float4 rqv = *(const float4*)&rq[(h * TR + j) * DK + sub * 4];
    const float4 rkv = *(const float4*)&rk[(h * TR + j) * DK + sub * 4];

    float p = qv.x * (kv.x + rkv.x) + rqv.x * kv.x
            + qv.y * (kv.y + rkv.y) + rqv.y * kv.y
            + qv.z * (kv.z + rkv.z) + rqv.z * kv.z
            + qv.w * (kv.w + rkv.w) + rqv.w * kv.w;
#pragma unroll
    for (int off = 8; off; off >>= 1)
        p += __shfl_xor_sync(0xffffffffu, p, off);

    if (sub == 0 && !masked) {
        float exv = __expf(p * (1.0f / 24.0f));
        g_e[e] = exv;
        atomicAdd(&g_cnt[bh * Ss + qn], 1);
    }
}

// ---------------- exclusive scan of per-node counts per (b,h) --------------
__global__ __launch_bounds__(256) void k_scan()
{
    __shared__ int partial[256];
    int bh = blockIdx.x;
    int t = threadIdx.x;
    int base = bh * Ss + t * 8;
    int c[8]; int sum = 0;
#pragma unroll
    for (int i = 0; i < 8; i++) { c[i] = g_cnt[base + i]; sum += c[i]; }
    partial[t] = sum;
    __syncthreads();
    for (int off = 1; off < 256; off <<= 1) {
        int v = (t >= off) ? partial[t - off] : 0;
        __syncthreads();
        partial[t] += v;
        __syncthreads();
    }
    int run = partial[t] - sum;
    int obase = bh * (Ss + 1) + t * 8;
#pragma unroll
    for (int i = 0; i < 8; i++) { g_off[obase + i] = run; run += c[i]; }
    if (t == 255) g_off[bh * (Ss + 1) + Ss] = run;
#pragma unroll
    for (int i = 0; i < 8; i++) g_cnt[base + i] = 0;
}

// ---------------- CSR fill ---------------------------------------------------
__global__ __launch_bounds__(256) void k_fill(
    const int* __restrict__ snod, const int* __restrict__ enod)
{
    int e = blockIdx.x * 256 + threadIdx.x;
    int s = e & (Ss - 1);
    int j = (e >> 11) & 15;
    int bh = e >> 15;
    int jm = j & (Rr - 1);
    int nidx = (bh * Rr + jm) * Ss + s;
    int sv = snod[nidx];
    if (j == 0 || sv < 0) return;
    int ev = enod[nidx];
    int qn = (j < Rr) ? ev : sv;
    int kn = (j < Rr) ? sv : ev;
    qn &= (Ss - 1); kn &= (Ss - 1);
    int pos = g_off[bh * (Ss + 1) + qn] + atomicAdd(&g_cnt[bh * Ss + qn], 1);
    int idx = bh * (TR * Ss) + pos;
    g_info[idx] = kn | (j << 12);
    g_val[idx] = g_e[e];
}

// ---------------- per-node gather + softmax + weighted sum -------------------
// writes fp16 attn directly (consumed by mode-1 GEMM)
__global__ __launch_bounds__(256) void k_aggr(const float* __restrict__ rv)
{
    int w = (blockIdx.x * 256 + threadIdx.x) >> 5;
    int lane = threadIdx.x & 31;
    int bh = w >> 11;
    int n = w & (Ss - 1);
    int h = bh & (Hh - 1), b = bh >> 3;
    int obase = bh * (Ss + 1) + n;
    int beg = g_off[obase], end = g_off[obase + 1];
    float acc0 = 0.f, acc1 = 0.f, ds = 0.f;
    int cbase = bh * (TR * Ss);
    for (int i = beg; i < end; i++) {
        int info = g_info[cbase + i];
        float evv = g_val[cbase + i];
        int kn = info & 0xFFF;
        int j = info >> 12;
        size_t vb = (size_t)(bh * Ss + kn) * DK;
        int rb = (h * TR + j) * DK;
        acc0 += evv * (g_v[vb + lane] + rv[rb + lane]);
        acc1 += evv * (g_v[vb + 32 + lane] + rv[rb + 32 + lane]);
        ds += evv;
    }
    float inv = ds > 0.f ? 1.f / ds : 0.f;
    size_t ob = (size_t)((b * Ss + n) * Hh + h) * DK;
    g_atth[ob + lane] = __float2half(acc0 * inv);
    g_atth[ob + 32 + lane] = __float2half(acc1 * inv);
}

// ---------------- launch --------------------------------------------------
#define GEMM_SMEM (4 * STAGE)

extern "C" void kernel_launch(void* const* d_in, const int* in_sizes, int n_in,
                              void* d_out, int out_size)
{
    const float* query = (const float*)d_in[0];
    const float* key   = (const float*)d_in[1];
    const float* value = (const float*)d_in[2];
    const int*   snod  = (const int*)d_in[3];
    const int*   enod  = (const int*)d_in[4];
    const float* rel_q = (const float*)d_in[5];
    const float* rel_k = (const float*)d_in[6];
    const float* rel_v = (const float*)d_in[7];
    const float* Wq = (const float*)d_in[8];
    const float* bq = (const float*)d_in[9];
    const float* Wk = (const float*)d_in[10];
    const float* bk = (const float*)d_in[11];
    const float* Wv = (const float*)d_in[12];
    const float* bv = (const float*)d_in[13];
    const float* Wo = (const float*)d_in[14];
    const float* bo = (const float*)d_in[15];
    float* out = (float*)d_out;

    cudaFuncSetAttribute(gemm_tc, cudaFuncAttributeMaxDynamicSharedMemorySize, GEMM_SMEM);

    dim3 gcw(Dd * Dd / 4 / 256, 4);           // weight convert
    dim3 gci(MROWS * Dd / 4 / 256, 3);        // input convert (+ g_cnt zero)
    dim3 gq(Dd / 64, MROWS / 128, 3);         // fused QKV
    dim3 go(Dd / 64, MROWS / 128, 1);         // output projection

    conv_w<<<gcw, 256>>>(Wq, Wk, Wv, Wo);
    conv_in<<<gci, 256>>>(query, key, value);
    gemm_tc<<<gq, 256, GEMM_SMEM>>>(bq, bk, bv, nullptr, 0);
    k_edges<<<(size_t)NEDGE * 16 / 256, 256>>>(snod, enod, rel_q, rel_k);
    k_scan<<<NBH, 256>>>();
    k_fill<<<NEDGE / 256, 256>>>(snod, enod);
    k_aggr<<<NNODES * 32 / 256, 256>>>(rel_v);
    gemm_tc<<<go, 256, GEMM_SMEM>>>(bo, nullptr, nullptr, out, 1);
}

// round 9
// speedup vs baseline: 1.6649x; 1.0579x over previous
#include <cuda_runtime.h>
#include <cuda_fp16.h>
#include <math.h>

// Problem constants (fixed by the dataset)
#define Bb   4
#define Ss   2048
#define Dd   512
#define Hh   8
#define DK   64
#define Rr   8
#define TR   16
#define NBH  (Bb*Hh)                // 32
#define NNODES (NBH*Ss)             // 65536
#define NEDGE  (NBH*TR*Ss)          // 1048576
#define MROWS (Bb*Ss)               // 8192

// ---------------- scratch (device globals; no allocation allowed) -------------
__device__ float g_q[NBH*Ss*DK];
__device__ float g_k[NBH*Ss*DK];
__device__ float g_v[NBH*Ss*DK];
__device__ int   g_cnt[NNODES];
__device__ int   g_off[NBH*(Ss+1)];
__device__ int   g_info[NEDGE];
__device__ __align__(16) __half g_ah[3*MROWS*Dd];   // fp16 inputs (q,k,v)
__device__ __align__(16) __half g_wh[4*Dd*Dd];      // weight hi
__device__ __align__(16) __half g_wl[4*Dd*Dd];      // weight lo
__device__ __align__(16) __half g_atth[MROWS*Dd];   // attn output fp16

// ======================= helpers =============================================
__device__ __forceinline__ unsigned su32(const void* p){
    unsigned a;
    asm("{ .reg .u64 t; cvta.to.shared.u64 t, %1; cvt.u32.u64 %0, t; }"
        : "=r"(a) : "l"(p));
    return a;
}
__device__ __forceinline__ void cpa16(unsigned dst, const void* src){
    asm volatile("cp.async.cg.shared.global [%0], [%1], 16;"
                 :: "r"(dst), "l"(src));
}
__device__ __forceinline__ void cpa_commit(){
    asm volatile("cp.async.commit_group;");
}
__device__ __forceinline__ void cpa_wait2(){
    asm volatile("cp.async.wait_group 2;");
}
__device__ __forceinline__ void ldmx4(unsigned* r, unsigned addr){
    asm volatile("ldmatrix.sync.aligned.m8n8.x4.shared.b16 {%0,%1,%2,%3}, [%4];"
                 : "=r"(r[0]), "=r"(r[1]), "=r"(r[2]), "=r"(r[3]) : "r"(addr));
}
__device__ __forceinline__ void mma_f16(float* d, const unsigned* a, const unsigned* b){
    asm volatile(
        "mma.sync.aligned.m16n8k16.row.col.f32.f16.f16.f32 "
        "{%0,%1,%2,%3}, {%4,%5,%6,%7}, {%8,%9}, {%0,%1,%2,%3};"
        : "+f"(d[0]), "+f"(d[1]), "+f"(d[2]), "+f"(d[3])
        : "r"(a[0]), "r"(a[1]), "r"(a[2]), "r"(a[3]), "r"(b[0]), "r"(b[1]));
}
// 64-byte rows, 16B-granule XOR swizzle: conflict-free ldmatrix
__device__ __forceinline__ unsigned swz(unsigned row, unsigned kb){
    return row * 64u + ((((kb >> 4) ^ ((row >> 1) & 3u)) << 4) | (kb & 15u));
}

// ---------------- conversion pre-passes --------------------------------------
__global__ __launch_bounds__(256) void conv_w(
    const float* __restrict__ Wq, const float* __restrict__ Wk,
    const float* __restrict__ Wv, const float* __restrict__ Wo)
{
    const int z = blockIdx.y;
    const float* W = (z == 0) ? Wq : (z == 1) ? Wk : (z == 2) ? Wv : Wo;
    const int i = blockIdx.x * 256 + threadIdx.x;
    float4 v = ((const float4*)W)[i];
    __half hx = __float2half(v.x), hy = __float2half(v.y);
    __half hz = __float2half(v.z), hw = __float2half(v.w);
    const size_t o = (size_t)z * (Dd*Dd) + (size_t)i * 4;
    *(__half2*)&g_wh[o]     = __halves2half2(hx, hy);
    *(__half2*)&g_wh[o + 2] = __halves2half2(hz, hw);
    *(__half2*)&g_wl[o]     = __halves2half2(__float2half(v.x - __half2float(hx)),
                                             __float2half(v.y - __half2float(hy)));
    *(__half2*)&g_wl[o + 2] = __halves2half2(__float2half(v.z - __half2float(hz)),
                                             __float2half(v.w - __half2float(hw)));
}

__global__ __launch_bounds__(256) void conv_in(
    const float* __restrict__ q, const float* __restrict__ k,
    const float* __restrict__ v)
{
    const int z = blockIdx.y;
    const float* X = (z == 0) ? q : (z == 1) ? k : v;
    const int i = blockIdx.x * 256 + threadIdx.x;
    if (z == 0 && i < NNODES) g_cnt[i] = 0;
    float4 val = ((const float4*)X)[i];
    const size_t o = (size_t)z * (MROWS*Dd) + (size_t)i * 4;
    *(__half2*)&g_ah[o]     = __floats2half2_rn(val.x, val.y);
    *(__half2*)&g_ah[o + 2] = __floats2half2_rn(val.z, val.w);
}

// ======== fp16 tensor-core GEMM (unchanged from R8) ==========================
#define STG_BH 8192
#define STG_BL 12288
#define STAGE  16384

__global__ __launch_bounds__(256, 2) void gemm_tc(
    const float* __restrict__ B0, const float* __restrict__ B1,
    const float* __restrict__ B2, float* __restrict__ C_ext, int mode)
{
    extern __shared__ char dsm[];
    const unsigned sb = su32(dsm);

    const int z = blockIdx.z;
    const __half* A;
    const __half* Wh;
    const __half* Wl;
    const float* bias;
    float* dst;
    if (mode == 0) {
        A = g_ah + (size_t)z * (MROWS*Dd);
        Wh = g_wh + (size_t)z * (Dd*Dd);
        Wl = g_wl + (size_t)z * (Dd*Dd);
        bias = (z == 0) ? B0 : (z == 1) ? B1 : B2;
        dst = (z == 0) ? g_q : (z == 1) ? g_k : g_v;
    } else {
        A = g_atth;
        Wh = g_wh + (size_t)3 * (Dd*Dd);
        Wl = g_wl + (size_t)3 * (Dd*Dd);
        bias = B0;
        dst = C_ext;
    }

    const int tid = threadIdx.x;
    const int wid = tid >> 5, lane = tid & 31;
    const int wm = wid & 3, wn = wid >> 2;
    const int m0 = blockIdx.y * 128, n0 = blockIdx.x * 64;

    const int arow = tid >> 1;
    const int ap0 = (2 * tid) & 3;
    const int brow = tid >> 2, bp = tid & 3;
    const __half* Asrc = A + (size_t)(m0 + arow) * Dd + ap0 * 8;
    const __half* Whsrc = Wh + (size_t)(n0 + brow) * Dd + bp * 8;
    const __half* Wlsrc = Wl + (size_t)(n0 + brow) * Dd + bp * 8;
    const unsigned dA0 = swz(arow, ap0 * 16);
    const unsigned dA1 = swz(arow, ap0 * 16 + 16);
    const unsigned dB  = swz(brow, bp * 16);

    float acc[2][4][4];
#pragma unroll
    for (int mt = 0; mt < 2; mt++)
#pragma unroll
        for (int nt = 0; nt < 4; nt++)
#pragma unroll
            for (int i = 0; i < 4; i++) acc[mt][nt][i] = 0.f;

#pragma unroll
    for (int c = 0; c < 3; c++) {
        const unsigned st = sb + c * STAGE;
        cpa16(st + dA0, Asrc + c * 32);
        cpa16(st + dA1, Asrc + c * 32 + 8);
        cpa16(st + STG_BH + dB, Whsrc + c * 32);
        cpa16(st + STG_BL + dB, Wlsrc + c * 32);
        cpa_commit();
    }

    for (int c = 0; c < 16; c++) {
        cpa_wait2();
        __syncthreads();
        if (c + 3 < 16) {
            const unsigned st = sb + ((c + 3) & 3) * STAGE;
            cpa16(st + dA0, Asrc + (c + 3) * 32);
            cpa16(st + dA1, Asrc + (c + 3) * 32 + 8);
            cpa16(st + STG_BH + dB, Whsrc + (c + 3) * 32);
            cpa16(st + STG_BL + dB, Wlsrc + (c + 3) * 32);
        }
        cpa_commit();

        const unsigned st = sb + (c & 3) * STAGE;
#pragma unroll
        for (int ks = 0; ks < 2; ks++) {
            const unsigned kb = ks * 32;
            unsigned ah[2][4], bh[4][2], bl[4][2];
#pragma unroll
            for (int mt = 0; mt < 2; mt++) {
                unsigned r = wm * 32 + mt * 16 + (lane & 15);
                unsigned kbyte = kb + (lane >> 4) * 16;
                ldmx4(ah[mt], st + swz(r, kbyte));
            }
#pragma unroll
            for (int p = 0; p < 2; p++) {
                unsigned r = wn * 32 + p * 16 + (lane & 7) + ((lane >> 4) << 3);
                unsigned kbyte = kb + ((lane >> 3) & 1) * 16;
                unsigned t[4];
                ldmx4(t, st + STG_BH + swz(r, kbyte));
                bh[2*p][0] = t[0]; bh[2*p][1] = t[1];
                bh[2*p+1][0] = t[2]; bh[2*p+1][1] = t[3];
                ldmx4(t, st + STG_BL + swz(r, kbyte));
                bl[2*p][0] = t[0]; bl[2*p][1] = t[1];
                bl[2*p+1][0] = t[2]; bl[2*p+1][1] = t[3];
            }
#pragma unroll
            for (int mt = 0; mt < 2; mt++)
#pragma unroll
                for (int nt = 0; nt < 4; nt++) {
                    mma_f16(acc[mt][nt], ah[mt], bh[nt]);
                    mma_f16(acc[mt][nt], ah[mt], bl[nt]);
                }
        }
        __syncthreads();
    }

#pragma unroll
    for (int nt = 0; nt < 4; nt++) {
        const int ncol = n0 + wn * 32 + nt * 8 + 2 * (lane & 3);
        const float b0 = bias[ncol], b1 = bias[ncol + 1];
#pragma unroll
        for (int mt = 0; mt < 2; mt++) {
            const int r0 = m0 + wm * 32 + mt * 16 + (lane >> 2);
            float2 v0 = make_float2(acc[mt][nt][0] + b0, acc[mt][nt][1] + b1);
            float2 v1 = make_float2(acc[mt][nt][2] + b0, acc[mt][nt][3] + b1);
            if (mode == 1) {
                *(float2*)(dst + (size_t)r0 * Dd + ncol) = v0;
                *(float2*)(dst + (size_t)(r0 + 8) * Dd + ncol) = v1;
            } else {
                const int h = ncol >> 6, d = ncol & 63;
                int b = r0 >> 11, s = r0 & (Ss - 1);
                *(float2*)(dst + (size_t)(((b * Hh + h) * Ss + s)) * DK + d) = v0;
                b = (r0 + 8) >> 11; s = (r0 + 8) & (Ss - 1);
                *(float2*)(dst + (size_t)(((b * Hh + h) * Ss + s)) * DK + d) = v1;
            }
        }
    }
}

// ---------------- per-edge counting (index-only) -----------------------------
// thread per (bh, jm, s): handles edge pair j=jm (q-node=end) and j=jm+8 (q-node=start)
__global__ __launch_bounds__(256) void k_count(
    const int* __restrict__ snod, const int* __restrict__ enod)
{
    int t = blockIdx.x * 256 + threadIdx.x;       // 524288
    int s = t & (Ss - 1);
    int jm = (t >> 11) & 7;
    int bh = t >> 14;
    int nidx = (bh * Rr + jm) * Ss + s;
    int sv = snod[nidx];
    if (sv < 0) return;
    int ev = enod[nidx] & (Ss - 1);
    int sv2 = sv & (Ss - 1);
    int base = bh * Ss;
    if (jm != 0) atomicAdd(&g_cnt[base + ev], 1);
    atomicAdd(&g_cnt[base + sv2], 1);
}

// ---------------- exclusive scan of per-node counts per (b,h) --------------
__global__ __launch_bounds__(256) void k_scan()
{
    __shared__ int partial[256];
    int bh = blockIdx.x;
    int t = threadIdx.x;
    int base = bh * Ss + t * 8;
    int c[8]; int sum = 0;
#pragma unroll
    for (int i = 0; i < 8; i++) { c[i] = g_cnt[base + i]; sum += c[i]; }
    partial[t] = sum;
    __syncthreads();
    for (int off = 1; off < 256; off <<= 1) {
        int v = (t >= off) ? partial[t - off] : 0;
        __syncthreads();
        partial[t] += v;
        __syncthreads();
    }
    int run = partial[t] - sum;
    int obase = bh * (Ss + 1) + t * 8;
#pragma unroll
    for (int i = 0; i < 8; i++) { g_off[obase + i] = run; run += c[i]; }
    if (t == 255) g_off[bh * (Ss + 1) + Ss] = run;
#pragma unroll
    for (int i = 0; i < 8; i++) g_cnt[base + i] = 0;
}

// ---------------- CSR fill (info only, no scores) ----------------------------
__global__ __launch_bounds__(256) void k_fill(
    const int* __restrict__ snod, const int* __restrict__ enod)
{
    int t = blockIdx.x * 256 + threadIdx.x;       // 524288
    int s = t & (Ss - 1);
    int jm = (t >> 11) & 7;
    int bh = t >> 14;
    int nidx = (bh * Rr + jm) * Ss + s;
    int sv = snod[nidx];
    if (sv < 0) return;
    int ev = enod[nidx] & (Ss - 1);
    int sv2 = sv & (Ss - 1);
    int base = bh * Ss;
    int cbase = bh * (TR * Ss);
    if (jm != 0) {
        int pos = g_off[bh * (Ss + 1) + ev] + atomicAdd(&g_cnt[base + ev], 1);
        g_info[cbase + pos] = sv2 | (jm << 12);            // q=ev, k=sv, j=jm
    }
    {
        int pos = g_off[bh * (Ss + 1) + sv2] + atomicAdd(&g_cnt[base + sv2], 1);
        g_info[cbase + pos] = ev | ((jm + 8) << 12);       // q=sv, k=ev, j=jm+8
    }
}

// --------- per-node: score + softmax + weighted sum in ONE pass --------------
// warp per node. q row loaded once; per entry: gather k row, score inside the
// butterfly reduce, exp on lane 0 only (MUFU budget), broadcast, accumulate.
__global__ __launch_bounds__(256) void k_aggr(
    const float* __restrict__ rq, const float* __restrict__ rk,
    const float* __restrict__ rv)
{
    int w = (blockIdx.x * 256 + threadIdx.x) >> 5;
    int lane = threadIdx.x & 31;
    int bh = w >> 11;
    int n = w & (Ss - 1);
    int h = bh & (Hh - 1), b = bh >> 3;
    int obase = bh * (Ss + 1) + n;
    int beg = g_off[obase], end = g_off[obase + 1];
    size_t qb = (size_t)(bh * Ss + n) * DK;
    float q0 = g_q[qb + lane], q1 = g_q[qb + 32 + lane];
    float acc0 = 0.f, acc1 = 0.f, ds = 0.f;
    int cbase = bh * (TR * Ss);
    for (int i = beg; i < end; i++) {
        int info = g_info[cbase + i];
        int kn = info & (Ss - 1);
        int j = info >> 12;
        size_t kb = (size_t)(bh * Ss + kn) * DK;
        int rb = (h * TR + j) * DK;
        float kv0 = g_k[kb + lane], kv1 = g_k[kb + 32 + lane];
        // score = q.(k+rk) + rq.k
        float p = q0 * (kv0 + rk[rb + lane]) + rq[rb + lane] * kv0
                + q1 * (kv1 + rk[rb + 32 + lane]) + rq[rb + 32 + lane] * kv1;
#pragma unroll
        for (int off = 16; off; off >>= 1)
            p += __shfl_xor_sync(0xffffffffu, p, off);
        float ev;
        if (lane == 0) ev = __expf(p * (1.0f / 24.0f));
        ev = __shfl_sync(0xffffffffu, ev, 0);
        acc0 += ev * (g_v[kb + lane] + rv[rb + lane]);
        acc1 += ev * (g_v[kb + 32 + lane] + rv[rb + 32 + lane]);
        ds += ev;
    }
    float inv = ds > 0.f ? 1.f / ds : 0.f;
    size_t ob = (size_t)((b * Ss + n) * Hh + h) * DK;
    g_atth[ob + lane] = __float2half(acc0 * inv);
    g_atth[ob + 32 + lane] = __float2half(acc1 * inv);
}

// ---------------- launch --------------------------------------------------
#define GEMM_SMEM (4 * STAGE)

extern "C" void kernel_launch(void* const* d_in, const int* in_sizes, int n_in,
                              void* d_out, int out_size)
{
    const float* query = (const float*)d_in[0];
    const float* key   = (const float*)d_in[1];
    const float* value = (const float*)d_in[2];
    const int*   snod  = (const int*)d_in[3];
    const int*   enod  = (const int*)d_in[4];
    const float* rel_q = (const float*)d_in[5];
    const float* rel_k = (const float*)d_in[6];
    const float* rel_v = (const float*)d_in[7];
    const float* Wq = (const float*)d_in[8];
    const float* bq = (const float*)d_in[9];
    const float* Wk = (const float*)d_in[10];
    const float* bk = (const float*)d_in[11];
    const float* Wv = (const float*)d_in[12];
    const float* bv = (const float*)d_in[13];
    const float* Wo = (const float*)d_in[14];
    const float* bo = (const float*)d_in[15];
    float* out = (float*)d_out;

    cudaFuncSetAttribute(gemm_tc, cudaFuncAttributeMaxDynamicSharedMemorySize, GEMM_SMEM);

    dim3 gcw(Dd * Dd / 4 / 256, 4);
    dim3 gci(MROWS * Dd / 4 / 256, 3);
    dim3 gq(Dd / 64, MROWS / 128, 3);
    dim3 go(Dd / 64, MROWS / 128, 1);

    conv_w<<<gcw, 256>>>(Wq, Wk, Wv, Wo);
    conv_in<<<gci, 256>>>(query, key, value);
    gemm_tc<<<gq, 256, GEMM_SMEM>>>(bq, bk, bv, nullptr, 0);
    k_count<<<(NBH * Rr * Ss) / 256, 256>>>(snod, enod);
    k_scan<<<NBH, 256>>>();
    k_fill<<<(NBH * Rr * Ss) / 256, 256>>>(snod, enod);
    k_aggr<<<NNODES * 32 / 256, 256>>>(rel_q, rel_k, rel_v);
    gemm_tc<<<go, 256, GEMM_SMEM>>>(bo, nullptr, nullptr, out, 1);
}